// round 3
// baseline (speedup 1.0000x reference)
#include <cuda_runtime.h>
#include <math.h>

#define NLAT 361
#define NLON 720
#define NBC  16        // 2 batches * 8 channels
#define NCH  32        // 2 tensors * 16 (complex channels)
#define KDEG 360       // degrees used: l = 0..359
#define EPSV 1e-7f
#define R_TOT  11552   // 2 tensors * 16 bc * 361 j
#define HALF_R 5776
#define PI_D 3.14159265358979323846

// ---------------- scratch (static device globals; no cudaMalloc allowed) ----
__device__ float2 g_B[NLON * NLAT];                       // [n][m] = {cos, -sin}  (~2 MB)
__device__ float2 g_F[(size_t)NLAT * NCH * NLAT];         // [m][c32][j] complex    (~33 MB)
__device__ float  g_stats[KDEG * NBC * 4];                // [l][bc]{pp,tp,sr,si}
__device__ float  g_wscale[NLAT];                         // w[j] * 2pi/720

// ---------------- f32x2 helpers --------------------------------------------
__device__ __forceinline__ unsigned long long pk2(float x, float y) {
    unsigned long long r;
    asm("mov.b64 %0, {%1, %2};" : "=l"(r) : "f"(x), "f"(y));
    return r;
}
__device__ __forceinline__ float2 upk2(unsigned long long v) {
    float2 r;
    asm("mov.b64 {%0, %1}, %2;" : "=f"(r.x), "=f"(r.y) : "l"(v));
    return r;
}
__device__ __forceinline__ void fma2(unsigned long long &d, unsigned long long a,
                                     unsigned long long b) {
    asm("fma.rn.f32x2 %0, %1, %2, %0;" : "+l"(d) : "l"(a), "l"(b));
}

// ---------------- K0: build twiddles, zero stats, scale vector --------------
__global__ void k0_init(const float* __restrict__ w) {
    int tid = blockIdx.x * blockDim.x + threadIdx.x;
    int stride = gridDim.x * blockDim.x;
    const int NB = NLON * NLAT;
    for (int i = tid; i < NB; i += stride) {
        int n = i / NLAT, m = i - (i / NLAT) * NLAT;
        int k = (int)(((long long)n * (long long)m) % NLON);
        double a = (double)k * (2.0 * PI_D / (double)NLON);
        g_B[i] = make_float2((float)cos(a), (float)(-sin(a)));
    }
    for (int i = tid; i < KDEG * NBC * 4; i += stride) g_stats[i] = 0.f;
    for (int i = tid; i < NLAT; i += stride)
        g_wscale[i] = w[i] * (float)(2.0 * PI_D / (double)NLON);
}

// ---------------- K1: DFT as tiled GEMM with f32x2 --------------------------
// out[r][m] = sum_n A[r][n] * {cos, -sin}(2pi m n / 720),  scaled by w[j]*2pi/720
// r = tensor*5776 + bc*361 + j ; output -> g_F[m][tensor*16+bc][j]
#define K1_BM 128
#define K1_BN 32
#define K1_BK 16

__global__ __launch_bounds__(128) void k1_dft(const float* __restrict__ pred,
                                              const float* __restrict__ targ) {
    __shared__ float  As[K1_BK][K1_BM];       // 8 KB
    __shared__ float2 Bs[K1_BK][K1_BN];       // 4 KB
    const int t    = threadIdx.x;
    const int m0   = blockIdx.x * K1_BN;
    const int row0 = blockIdx.y * K1_BM;
    const int trow = t >> 3;   // 0..15  (8 rows each)
    const int tcol = t & 7;    // 0..7   (4 m-cols each)

    unsigned long long acc[8][4];
    const unsigned long long z = pk2(0.f, 0.f);
#pragma unroll
    for (int i = 0; i < 8; i++)
#pragma unroll
        for (int j = 0; j < 4; j++) acc[i][j] = z;

    const int r = row0 + t;
    const float* abase = nullptr;
    if (r < R_TOT) {
        int tensor = r / HALF_R;
        int rem = r - tensor * HALF_R;
        abase = (tensor ? targ : pred) + (size_t)rem * NLON;
    }

    for (int k0 = 0; k0 < NLON; k0 += K1_BK) {
        if (abase) {
#pragma unroll
            for (int q = 0; q < 4; q++) {
                float4 v = *reinterpret_cast<const float4*>(abase + k0 + q * 4);
                As[q * 4 + 0][t] = v.x; As[q * 4 + 1][t] = v.y;
                As[q * 4 + 2][t] = v.z; As[q * 4 + 3][t] = v.w;
            }
        } else {
#pragma unroll
            for (int kk = 0; kk < K1_BK; kk++) As[kk][t] = 0.f;
        }
#pragma unroll
        for (int q = 0; q < 4; q++) {
            int i  = t + q * 128;
            int kb = i >> 5, mb = i & 31;
            int mg = m0 + mb;
            float2 v = (mg < NLAT) ? g_B[(size_t)(k0 + kb) * NLAT + mg]
                                   : make_float2(0.f, 0.f);
            Bs[kb][mb] = v;
        }
        __syncthreads();
#pragma unroll
        for (int kk = 0; kk < K1_BK; kk++) {
            unsigned long long bv[4];
#pragma unroll
            for (int j = 0; j < 4; j++)
                bv[j] = *reinterpret_cast<const unsigned long long*>(
                    &Bs[kk][tcol * 4 + j]);
#pragma unroll
            for (int i = 0; i < 8; i++) {
                float av = As[kk][trow * 8 + i];
                unsigned long long aa = pk2(av, av);
#pragma unroll
                for (int j = 0; j < 4; j++) fma2(acc[i][j], aa, bv[j]);
            }
        }
        __syncthreads();
    }

    // epilogue: scale by w[j]*2pi/720 and scatter to g_F[m][c][j]
#pragma unroll
    for (int i = 0; i < 8; i++) {
        int rr = row0 + trow * 8 + i;
        if (rr >= R_TOT) continue;
        int tensor = rr / HALF_R;
        int rem = rr - tensor * HALF_R;
        int bc = rem / NLAT;
        int jj = rem - bc * NLAT;
        float sc = g_wscale[jj];
        int c = tensor * 16 + bc;
#pragma unroll
        for (int j = 0; j < 4; j++) {
            int m = m0 + tcol * 4 + j;
            if (m >= NLAT) continue;
            float2 v = upk2(acc[i][j]);
            g_F[((size_t)m * NCH + c) * NLAT + jj] = make_float2(v.x * sc, v.y * sc);
        }
    }
}

// ---------------- K2: Legendre contraction + per-degree stats ---------------
// Block = (m, tile of 64 l's). For each l,ch: C = sum_j leg[l][m][j] * F[m][ch][j]
// Then accumulate pp/tp/sr/si into g_stats with m-weight (m==0 ? 1 : 2).
#define TL  64
#define TJ  16
#define FSP 33

__global__ __launch_bounds__(128) void k2_leg(const float* __restrict__ leg) {
    const int m  = blockIdx.y;                 // 0..359
    const int l0 = m + blockIdx.x * TL;
    if (l0 >= KDEG) return;

    __shared__ float2 Fs[TJ][FSP];             // [j][ch], padded
    __shared__ float  Ls[TL][TJ + 1];          // [l][j], padded
    __shared__ float2 res[TL][NCH];            // 16 KB

    const int t   = threadIdx.x;
    const int cg  = t & 7;                     // 8 ch-groups of 4
    const int lg  = t >> 3;                    // 16 l-groups of 4
    const int ch0 = cg * 4;
    const int lb  = lg * 4;

    unsigned long long acc[4][4];
    const unsigned long long z = pk2(0.f, 0.f);
#pragma unroll
    for (int i = 0; i < 4; i++)
#pragma unroll
        for (int k = 0; k < 4; k++) acc[i][k] = z;

    for (int j0 = 0; j0 < NLAT; j0 += TJ) {
#pragma unroll
        for (int q = 0; q < 4; q++) {          // stage F tile: 512 float2
            int p = t + q * 128;
            int c = p >> 4, jl = p & 15;
            int j = j0 + jl;
            Fs[jl][c] = (j < NLAT) ? g_F[((size_t)m * NCH + c) * NLAT + j]
                                   : make_float2(0.f, 0.f);
        }
#pragma unroll
        for (int q = 0; q < 8; q++) {          // stage leg tile: 1024 floats
            int p  = t + q * 128;
            int lr = p >> 4, jl = p & 15;
            int j  = j0 + jl;
            int l  = l0 + lr; if (l > 360) l = 360;   // clamp (unused rows)
            Ls[lr][jl] = (j < NLAT) ? leg[((size_t)l * NLAT + m) * NLAT + j] : 0.f;
        }
        __syncthreads();
#pragma unroll
        for (int jl = 0; jl < TJ; jl++) {
            unsigned long long fv[4];
#pragma unroll
            for (int k = 0; k < 4; k++)
                fv[k] = *reinterpret_cast<const unsigned long long*>(&Fs[jl][ch0 + k]);
#pragma unroll
            for (int i = 0; i < 4; i++) {
                float lv = Ls[lb + i][jl];
                unsigned long long aa = pk2(lv, lv);
#pragma unroll
                for (int k = 0; k < 4; k++) fma2(acc[i][k], aa, fv[k]);
            }
        }
        __syncthreads();
    }

#pragma unroll
    for (int i = 0; i < 4; i++)
#pragma unroll
        for (int k = 0; k < 4; k++) res[lb + i][ch0 + k] = upk2(acc[i][k]);
    __syncthreads();

    const float wm = (m == 0) ? 1.f : 2.f;
#pragma unroll
    for (int q = 0; q < 8; q++) {
        int p  = t + q * 128;                  // 1024 (l, bc) pairs
        int lr = p >> 4, bc = p & 15;
        int l  = l0 + lr;
        if (l >= KDEG) continue;
        float2 cP = res[lr][bc];
        float2 cT = res[lr][16 + bc];
        float pp  = cP.x * cP.x + cP.y * cP.y;
        float tp  = cT.x * cT.x + cT.y * cT.y;
        float crr = cP.x * cT.x + cP.y * cT.y;
        float cii = cP.x * cT.y - cP.y * cT.x;
        float* s = &g_stats[(l * NBC + bc) * 4];
        atomicAdd(s + 0, wm * pp);
        atomicAdd(s + 1, wm * tp);
        atomicAdd(s + 2, wm * crr);
        atomicAdd(s + 3, wm * cii);
    }
}

// ---------------- K3: final loss --------------------------------------------
__global__ void k3_final(const float* __restrict__ weights, float* __restrict__ out) {
    __shared__ float red[256];
    const int t = threadIdx.x;
    float part = 0.f;
    for (int idx = t; idx < KDEG * NBC; idx += 256) {
        int bc = idx / KDEG;
        int l  = idx - bc * KDEG;
        const float* s = &g_stats[(l * NBC + bc) * 4];
        float pp = s[0] + EPSV;
        float tp = s[1] + EPSV;
        float sr = s[2], si = s[3];
        float mag = sqrtf(sr * sr + si * si);
        float den = sqrtf(pp * tp + EPSV) + EPSV;
        float coh = fminf(mag / den, 1.f);
        float sp = sqrtf(pp), st_ = sqrtf(tp);
        float amp = (sp - st_) * (sp - st_);
        float dec = 2.f * fmaxf(pp, tp) * (1.f - coh);
        part += weights[bc & 7] * (amp + dec);
    }
    red[t] = part;
    __syncthreads();
    for (int s2 = 128; s2 > 0; s2 >>= 1) {
        if (t < s2) red[t] += red[t + s2];
        __syncthreads();
    }
    if (t == 0) {
        float loss = red[0] / (float)(KDEG * NBC);
        if (isnan(loss)) loss = 1e6f;
        out[0] = loss;
    }
}

// ---------------- launcher ---------------------------------------------------
extern "C" void kernel_launch(void* const* d_in, const int* in_sizes, int n_in,
                              void* d_out, int out_size) {
    const float* pred    = (const float*)d_in[0];
    const float* targ    = (const float*)d_in[1];
    const float* weights = (const float*)d_in[2];
    const float* leg     = (const float*)d_in[3];
    const float* w       = (const float*)d_in[4];

    k0_init<<<512, 256>>>(w);

    dim3 g1((NLAT + K1_BN - 1) / K1_BN, (R_TOT + K1_BM - 1) / K1_BM);  // (12, 91)
    k1_dft<<<g1, 128>>>(pred, targ);

    dim3 g2((KDEG + TL - 1) / TL, KDEG);                               // (6, 360)
    k2_leg<<<g2, 128>>>(leg);

    k3_final<<<1, 256>>>(weights, (float*)d_out);
}

// round 5
// speedup vs baseline: 1.2721x; 1.2721x over previous
#include <cuda_runtime.h>
#include <math.h>

#define NLAT 361
#define NLON 720
#define NBC  16        // 2 batches * 8 channels
#define NCH  32        // 2 tensors * 16 complex channels
#define KDEG 360       // degrees used: l = 0..359
#define EPSV 1e-7f
#define R_TOT  11552   // 2 tensors * 16 bc * 361 j
#define R_PAD  11584   // 181 * 64
#define HALF_R 5776
#define NPAD   384     // padded folded-K dimension (n = 0..360 real)
#define MPPAD  192     // padded m-pair dimension (m-pairs 0..180 real)
#define PI_F 3.14159265358979323846f

typedef unsigned long long ull;

// ---------------- scratch (static device globals; no cudaMalloc allowed) ----
__device__ float  g_S[(size_t)R_PAD * NPAD];              // folded sums  (17.8 MB)
__device__ float  g_D[(size_t)R_PAD * NPAD];              // folded diffs (17.8 MB)
__device__ float2 g_Bc[NPAD * MPPAD];                     // {cos(m0),cos(m1)}
__device__ float2 g_Bs[NPAD * MPPAD];                     // {-sin(m0),-sin(m1)}
__device__ float2 g_F[(size_t)NLAT * NCH * NLAT];         // [m][c32][j]  (33.4 MB)
__device__ float  g_stats[KDEG * NBC * 4];                // [l][bc]{pp,tp,sr,si}

// ---------------- f32x2 helpers --------------------------------------------
__device__ __forceinline__ ull pk2(float x, float y) {
    ull r;
    asm("mov.b64 %0, {%1, %2};" : "=l"(r) : "f"(x), "f"(y));
    return r;
}
__device__ __forceinline__ float2 upk2(ull v) {
    float2 r;
    asm("mov.b64 {%0, %1}, %2;" : "=f"(r.x), "=f"(r.y) : "l"(v));
    return r;
}
__device__ __forceinline__ void fma2(ull &d, ull a, ull b) {
    asm("fma.rn.f32x2 %0, %1, %2, %0;" : "+l"(d) : "l"(a), "l"(b));
}

// ---------------- K0a: twiddle tables (m-pair packed) + zero stats ----------
__global__ void k0_tables() {
    int tid = blockIdx.x * blockDim.x + threadIdx.x;
    int stride = gridDim.x * blockDim.x;
    const int NT = NPAD * MPPAD;
    for (int i = tid; i < NT; i += stride) {
        int n = i / MPPAD, mp = i - (i / MPPAD) * MPPAD;
        float c0 = 0.f, s0 = 0.f, c1 = 0.f, s1 = 0.f;
        if (n <= 360) {
            int m0 = 2 * mp, m1 = m0 + 1;
            if (m0 <= 360) {
                float s, c;
                sincospif((float)((n * m0) % NLON) / 360.f, &s, &c);
                c0 = c; s0 = -s;
            }
            if (m1 <= 360) {
                float s, c;
                sincospif((float)((n * m1) % NLON) / 360.f, &s, &c);
                c1 = c; s1 = -s;
            }
        }
        g_Bc[i] = make_float2(c0, c1);
        g_Bs[i] = make_float2(s0, s1);
    }
    for (int i = tid; i < KDEG * NBC * 4; i += stride) g_stats[i] = 0.f;
}

// ---------------- K0b: fold rows into sum/diff with quadrature scale --------
// s[n] = (a[n] + a[720-n]) * w[j]*2pi/720  (n=1..359), s[0]=a[0]*wsc, s[360]=a[360]*wsc
// d[n] = (a[n] - a[720-n]) * wsc           (n=1..359), else 0.  Pad rows/cols zeroed.
__global__ void k0b_sd(const float* __restrict__ pred,
                       const float* __restrict__ targ,
                       const float* __restrict__ w) {
    const int NQ = NPAD / 4;  // 96 float4 per row
    int id = blockIdx.x * blockDim.x + threadIdx.x;
    if (id >= R_PAD * NQ) return;
    int r = id / NQ;
    int n = (id - r * NQ) * 4;
    float4 sv = make_float4(0.f, 0.f, 0.f, 0.f);
    float4 dv = make_float4(0.f, 0.f, 0.f, 0.f);
    if (r < R_TOT) {
        int tensor = r / HALF_R;
        int rem = r - tensor * HALF_R;
        int j = rem % NLAT;
        float wsc = w[j] * (2.f * PI_F / (float)NLON);
        const float* a = (tensor ? targ : pred) + (size_t)rem * NLON;
        float4 af = *(const float4*)(a + n);     // n <= 380 < 717: always in-bounds
        float fa[4] = {af.x, af.y, af.z, af.w};
        float so[4], dd[4];
#pragma unroll
        for (int e = 0; e < 4; e++) {
            int nn = n + e;
            float av = (nn <= 360) ? fa[e] : 0.f;
            float mv = (nn >= 1 && nn <= 359) ? a[NLON - nn] : 0.f;
            so[e] = (av + mv) * wsc;
            dd[e] = (av - mv) * wsc;
        }
        sv = make_float4(so[0], so[1], so[2], so[3]);
        dv = make_float4(dd[0], dd[1], dd[2], dd[3]);
    }
    *(float4*)&g_S[(size_t)r * NPAD + n] = sv;
    *(float4*)&g_D[(size_t)r * NPAD + n] = dv;
}

// ---------------- K1: folded DFT as two real GEMMs, f32x2 over m-pairs ------
// Block: 64 rows x 32 m-pairs (64 m). Thread: 4 rows x 4 mp x {cos,sin} accs.
__global__ __launch_bounds__(128) void k1_dft() {
    __shared__ float  Ss[64][36];     // [row][kk], padded stride (9 KB)
    __shared__ float  Ds[64][36];
    __shared__ float2 Cs[32][32];     // [kk][mp]  (8 KB)
    __shared__ float2 Sn[32][32];

    const int t    = threadIdx.x;
    const int mp0  = blockIdx.x * 32;
    const int row0 = blockIdx.y * 64;
    const int tcol = t & 7;           // mp group (4 each)
    const int trow = t >> 3;          // row group (4 each)

    ull aC[4][4], aS[4][4];
    const ull z = pk2(0.f, 0.f);
#pragma unroll
    for (int i = 0; i < 4; i++)
#pragma unroll
        for (int j = 0; j < 4; j++) { aC[i][j] = z; aS[i][j] = z; }

    for (int kt = 0; kt < 12; kt++) {
        const int k0 = kt * 32;
        // stage S/D: 64 rows x 32 n, full-line coalesced
#pragma unroll
        for (int q = 0; q < 4; q++) {
            int rl = (t >> 3) + q * 16;
            int f4 = (t & 7) * 4;
            size_t gi = (size_t)(row0 + rl) * NPAD + k0 + f4;
            *(float4*)&Ss[rl][f4] = *(const float4*)&g_S[gi];
            *(float4*)&Ds[rl][f4] = *(const float4*)&g_D[gi];
        }
        // stage twiddle tiles
#pragma unroll
        for (int q = 0; q < 4; q++) {
            int e = t + q * 128;
            int nl = e >> 4, f4 = e & 15;
            size_t gi = (size_t)(k0 + nl) * MPPAD + mp0;
            ((float4*)&Cs[nl][0])[f4] = ((const float4*)&g_Bc[gi])[f4];
            ((float4*)&Sn[nl][0])[f4] = ((const float4*)&g_Bs[gi])[f4];
        }
        __syncthreads();
#pragma unroll 8
        for (int kk = 0; kk < 32; kk++) {
            ulonglong2 c01 = *(const ulonglong2*)&Cs[kk][tcol * 4];
            ulonglong2 c23 = *(const ulonglong2*)&Cs[kk][tcol * 4 + 2];
            ulonglong2 s01 = *(const ulonglong2*)&Sn[kk][tcol * 4];
            ulonglong2 s23 = *(const ulonglong2*)&Sn[kk][tcol * 4 + 2];
#pragma unroll
            for (int i = 0; i < 4; i++) {
                float sv = Ss[trow * 4 + i][kk];
                float dv = Ds[trow * 4 + i][kk];
                ull sa = pk2(sv, sv), da = pk2(dv, dv);
                fma2(aC[i][0], sa, c01.x); fma2(aC[i][1], sa, c01.y);
                fma2(aC[i][2], sa, c23.x); fma2(aC[i][3], sa, c23.y);
                fma2(aS[i][0], da, s01.x); fma2(aS[i][1], da, s01.y);
                fma2(aS[i][2], da, s23.x); fma2(aS[i][3], da, s23.y);
            }
        }
        __syncthreads();
    }

    // epilogue: Re = aC, Im = aS (sign folded into table); scatter to g_F[m][c][j]
#pragma unroll
    for (int i = 0; i < 4; i++) {
        int gr = row0 + trow * 4 + i;
        if (gr >= R_TOT) continue;
        int tensor = gr / HALF_R;
        int rem = gr - tensor * HALF_R;
        int bc = rem / NLAT;
        int j  = rem - bc * NLAT;
        int c  = tensor * 16 + bc;
#pragma unroll
        for (int jj = 0; jj < 4; jj++) {
            int mp = mp0 + tcol * 4 + jj;
            int m0 = 2 * mp;
            float2 vc = upk2(aC[i][jj]);
            float2 vs = upk2(aS[i][jj]);
            if (m0 <= 360)
                g_F[((size_t)m0 * NCH + c) * NLAT + j] = make_float2(vc.x, vs.x);
            if (m0 + 1 <= 360)
                g_F[((size_t)(m0 + 1) * NCH + c) * NLAT + j] = make_float2(vc.y, vs.y);
        }
    }
}

// ---------------- K2: Legendre contraction with equatorial parity fold ------
// Block = (m, 64 l's). Parity of (l+m) == (i&1) of register row (compile-time).
#define TJ 16
__global__ __launch_bounds__(128) void k2_leg(const float* __restrict__ leg) {
    const int m  = blockIdx.y;                 // 0..359
    const int l0 = m + blockIdx.x * 64;
    if (l0 >= KDEG) return;

    __shared__ float2 Fse[TJ][34];             // even-fold F, [j][ch]
    __shared__ float2 Fso[TJ][34];             // odd-fold F
    __shared__ float2 Ls2[64][17];             // leg broadcast pairs {v,v}
    __shared__ float2 res[64][NCH];            // 16 KB

    const int t   = threadIdx.x;
    const int cg  = t & 7;
    const int lg  = t >> 3;
    const int ch0 = cg * 4;
    const int lb  = lg * 4;

    ull acc[4][4];
    const ull z = pk2(0.f, 0.f);
#pragma unroll
    for (int i = 0; i < 4; i++)
#pragma unroll
        for (int k = 0; k < 4; k++) acc[i][k] = z;

    const float2* Fm = &g_F[(size_t)m * NCH * NLAT];

    for (int j0 = 0; j0 < 181; j0 += TJ) {     // 12 tiles
#pragma unroll
        for (int q = 0; q < 4; q++) {
            int p = t + q * 128;
            int c = p >> 4, jl = p & 15;
            int j = j0 + jl;
            float2 f  = (j <= 180) ? Fm[(size_t)c * NLAT + j]       : make_float2(0.f, 0.f);
            float2 fm = (j <  180) ? Fm[(size_t)c * NLAT + 360 - j] : make_float2(0.f, 0.f);
            Fse[jl][c] = make_float2(f.x + fm.x, f.y + fm.y);
            Fso[jl][c] = make_float2(f.x - fm.x, f.y - fm.y);
        }
#pragma unroll
        for (int q = 0; q < 8; q++) {
            int p  = t + q * 128;
            int lr = p >> 4, jl = p & 15;
            int j  = j0 + jl;
            int l  = l0 + lr;
            float v = (j <= 180 && l <= 360) ? leg[((size_t)l * NLAT + m) * NLAT + j] : 0.f;
            Ls2[lr][jl] = make_float2(v, v);
        }
        __syncthreads();
#pragma unroll
        for (int jl = 0; jl < TJ; jl++) {
            ulonglong2 fe01 = *(const ulonglong2*)&Fse[jl][ch0];
            ulonglong2 fe23 = *(const ulonglong2*)&Fse[jl][ch0 + 2];
            ulonglong2 fo01 = *(const ulonglong2*)&Fso[jl][ch0];
            ulonglong2 fo23 = *(const ulonglong2*)&Fso[jl][ch0 + 2];
#pragma unroll
            for (int i = 0; i < 4; i++) {
                ull lv = *(const ull*)&Ls2[lb + i][jl];
                if (i & 1) {
                    fma2(acc[i][0], lv, fo01.x); fma2(acc[i][1], lv, fo01.y);
                    fma2(acc[i][2], lv, fo23.x); fma2(acc[i][3], lv, fo23.y);
                } else {
                    fma2(acc[i][0], lv, fe01.x); fma2(acc[i][1], lv, fe01.y);
                    fma2(acc[i][2], lv, fe23.x); fma2(acc[i][3], lv, fe23.y);
                }
            }
        }
        __syncthreads();
    }

#pragma unroll
    for (int i = 0; i < 4; i++)
#pragma unroll
        for (int k = 0; k < 4; k++) res[lb + i][ch0 + k] = upk2(acc[i][k]);
    __syncthreads();

    const float wm = (m == 0) ? 1.f : 2.f;
#pragma unroll
    for (int q = 0; q < 8; q++) {
        int p  = t + q * 128;                  // 1024 (l, bc) pairs
        int lr = p >> 4, bc = p & 15;
        int l  = l0 + lr;
        if (l >= KDEG) continue;
        float2 cP = res[lr][bc];
        float2 cT = res[lr][16 + bc];
        float pp  = cP.x * cP.x + cP.y * cP.y;
        float tp  = cT.x * cT.x + cT.y * cT.y;
        float crr = cP.x * cT.x + cP.y * cT.y;
        float cii = cP.x * cT.y - cP.y * cT.x;
        float* s = &g_stats[(l * NBC + bc) * 4];
        atomicAdd(s + 0, wm * pp);
        atomicAdd(s + 1, wm * tp);
        atomicAdd(s + 2, wm * crr);
        atomicAdd(s + 3, wm * cii);
    }
}

// ---------------- K3: final loss --------------------------------------------
__global__ void k3_final(const float* __restrict__ weights, float* __restrict__ out) {
    __shared__ float red[32];
    const int t = threadIdx.x;                 // 1024 threads
    float part = 0.f;
    for (int i = t; i < KDEG * NBC; i += 1024) {
        float4 s = *(const float4*)&g_stats[i * 4];
        int bc = i & 15;
        float pp = s.x + EPSV;
        float tp = s.y + EPSV;
        float mag = sqrtf(s.z * s.z + s.w * s.w);
        float den = sqrtf(pp * tp + EPSV) + EPSV;
        float coh = fminf(mag / den, 1.f);
        float sp = sqrtf(pp), st = sqrtf(tp);
        float amp = (sp - st) * (sp - st);
        float dec = 2.f * fmaxf(pp, tp) * (1.f - coh);
        part += weights[bc & 7] * (amp + dec);
    }
#pragma unroll
    for (int o = 16; o > 0; o >>= 1) part += __shfl_down_sync(0xffffffffu, part, o);
    if ((t & 31) == 0) red[t >> 5] = part;
    __syncthreads();
    if (t < 32) {
        float v = red[t];
#pragma unroll
        for (int o = 16; o > 0; o >>= 1) v += __shfl_down_sync(0xffffffffu, v, o);
        if (t == 0) {
            float loss = v / (float)(KDEG * NBC);
            if (isnan(loss)) loss = 1e6f;
            out[0] = loss;
        }
    }
}

// ---------------- launcher ---------------------------------------------------
extern "C" void kernel_launch(void* const* d_in, const int* in_sizes, int n_in,
                              void* d_out, int out_size) {
    const float* pred    = (const float*)d_in[0];
    const float* targ    = (const float*)d_in[1];
    const float* weights = (const float*)d_in[2];
    const float* leg     = (const float*)d_in[3];
    const float* w       = (const float*)d_in[4];

    k0_tables<<<256, 256>>>();

    int tot0 = R_PAD * (NPAD / 4);
    k0b_sd<<<(tot0 + 255) / 256, 256>>>(pred, targ, w);

    dim3 g1(6, 181);            // 6 mp-tiles (192 mp) x 181 row-tiles
    k1_dft<<<g1, 128>>>();

    dim3 g2(6, KDEG);           // l-tiles x m
    k2_leg<<<g2, 128>>>(leg);

    k3_final<<<1, 1024>>>(weights, (float*)d_out);
}

// round 6
// speedup vs baseline: 1.8085x; 1.4217x over previous
#include <cuda_runtime.h>
#include <math.h>

#define NLAT 361
#define NLON 720
#define NBC  16        // 2 batches * 8 channels
#define NCH  32        // 2 tensors * 16 complex channels
#define KDEG 360
#define EPSV 1e-7f
#define R_TOT  11552
#define R_PAD  11584   // 362 * 32
#define HALF_R 5776
#define NPAD   384     // padded folded-n dimension (n = 0..360 real)
#define MP2    96      // padded m-pair count (mp 0..90 real -> m 0..181)
#define PI_F 3.14159265358979323846f

typedef unsigned long long ull;

// ---------------- scratch ----------------------------------------------------
__device__ float  g_S[(size_t)R_PAD * NPAD];              // folded sums
__device__ float  g_D[(size_t)R_PAD * NPAD];              // folded diffs
__device__ float2 g_Bc[NPAD * MP2];                       // {cos(m0),cos(m1)}
__device__ float2 g_Bs[NPAD * MP2];                       // {-sin(m0),-sin(m1)}
__device__ float2 g_F[(size_t)NLAT * NCH * NLAT];         // [m][c32][j]
__device__ float  g_stats[KDEG * NBC * 4];                // [l][bc]{pp,tp,sr,si}

// ---------------- f32x2 helpers ---------------------------------------------
__device__ __forceinline__ ull pk2(float x, float y) {
    ull r; asm("mov.b64 %0, {%1, %2};" : "=l"(r) : "f"(x), "f"(y)); return r;
}
__device__ __forceinline__ float2 upk2(ull v) {
    float2 r; asm("mov.b64 {%0, %1}, %2;" : "=f"(r.x), "=f"(r.y) : "l"(v)); return r;
}
__device__ __forceinline__ void fma2(ull &d, ull a, ull b) {
    asm("fma.rn.f32x2 %0, %1, %2, %0;" : "+l"(d) : "l"(a), "l"(b));
}

// ---------------- K0a: twiddle tables (m 0..181) + zero stats ---------------
__global__ void k0_tables() {
    int tid = blockIdx.x * blockDim.x + threadIdx.x;
    int stride = gridDim.x * blockDim.x;
    const int NT = NPAD * MP2;
    for (int i = tid; i < NT; i += stride) {
        int n = i / MP2, mp = i - (i / MP2) * MP2;
        float c0 = 0.f, s0 = 0.f, c1 = 0.f, s1 = 0.f;
        if (n <= 360) {
            int m0 = 2 * mp, m1 = m0 + 1;
            if (m0 <= 181) {
                float s, c;
                sincospif((float)((n * m0) % NLON) / 360.f, &s, &c);
                c0 = c; s0 = -s;
            }
            if (m1 <= 181) {
                float s, c;
                sincospif((float)((n * m1) % NLON) / 360.f, &s, &c);
                c1 = c; s1 = -s;
            }
        }
        g_Bc[i] = make_float2(c0, c1);
        g_Bs[i] = make_float2(s0, s1);
    }
    for (int i = tid; i < KDEG * NBC * 4; i += stride) g_stats[i] = 0.f;
}

// ---------------- K0b: fold rows into sum/diff with quadrature scale --------
__global__ void k0b_sd(const float* __restrict__ pred,
                       const float* __restrict__ targ,
                       const float* __restrict__ w) {
    const int NQ = NPAD / 4;  // 96 float4 per row
    int id = blockIdx.x * blockDim.x + threadIdx.x;
    if (id >= R_PAD * NQ) return;
    int r = id / NQ;
    int n = (id - r * NQ) * 4;
    float4 sv = make_float4(0.f, 0.f, 0.f, 0.f);
    float4 dv = make_float4(0.f, 0.f, 0.f, 0.f);
    if (r < R_TOT) {
        int tensor = r / HALF_R;
        int rem = r - tensor * HALF_R;
        int j = rem % NLAT;
        float wsc = w[j] * (2.f * PI_F / (float)NLON);
        const float* a = (tensor ? targ : pred) + (size_t)rem * NLON;
        float4 af = *(const float4*)(a + n);
        float fa[4] = {af.x, af.y, af.z, af.w};
        float so[4], dd[4];
#pragma unroll
        for (int e = 0; e < 4; e++) {
            int nn = n + e;
            float av = (nn <= 360) ? fa[e] : 0.f;
            float mv = (nn >= 1 && nn <= 359) ? a[NLON - nn] : 0.f;
            so[e] = (av + mv) * wsc;
            dd[e] = (av - mv) * wsc;
        }
        sv = make_float4(so[0], so[1], so[2], so[3]);
        dv = make_float4(dd[0], dd[1], dd[2], dd[3]);
    }
    *(float4*)&g_S[(size_t)r * NPAD + n] = sv;
    *(float4*)&g_D[(size_t)r * NPAD + n] = dv;
}

// ---------------- K1: folded DFT with m <-> 360-m mirror fold ---------------
// Even/odd n partial sums (Ce,Co,Se,So) give F[m] = Ce+Co / Se+So and
// F[360-m] = Ce-Co / -Se+So. Block: 32 rows x 32 mp (m-pairs, 64 m + mirrors).
// Thread: 4 rows x 2 mp x 4 partial sets = 32 f32x2 accumulators.
__global__ __launch_bounds__(128) void k1_dft() {
    __shared__ float2 Ss[32][16];     // [row][q] = {s[2q], s[2q+1]}  (4 KB)
    __shared__ float2 Ds[32][16];
    __shared__ float2 Cs[32][32];     // [n_local][mp]                (8 KB)
    __shared__ float2 Sn[32][32];

    const int t    = threadIdx.x;
    const int mp0  = blockIdx.x * 32;
    const int row0 = blockIdx.y * 32;
    const int tcol = t & 15;          // 16 groups x 2 mp
    const int trow = t >> 4;          // 8 groups x 4 rows
    const int tc2  = tcol * 2;

    ull aCe[4][2], aCo[4][2], aSe[4][2], aSo[4][2];
    const ull z = pk2(0.f, 0.f);
#pragma unroll
    for (int i = 0; i < 4; i++)
#pragma unroll
        for (int p = 0; p < 2; p++) {
            aCe[i][p] = z; aCo[i][p] = z; aSe[i][p] = z; aSo[i][p] = z;
        }

    for (int kt = 0; kt < 12; kt++) {
        const int k0 = kt * 32;
        // stage S/D: 32 rows x 32 n (256 float4 each)
#pragma unroll
        for (int q = 0; q < 2; q++) {
            int f = t + q * 128;
            int row = f >> 3, c4 = f & 7;
            size_t gi = (size_t)(row0 + row) * NPAD + k0 + c4 * 4;
            float4 v = *(const float4*)&g_S[gi];
            Ss[row][c4 * 2]     = make_float2(v.x, v.y);
            Ss[row][c4 * 2 + 1] = make_float2(v.z, v.w);
            float4 u = *(const float4*)&g_D[gi];
            Ds[row][c4 * 2]     = make_float2(u.x, u.y);
            Ds[row][c4 * 2 + 1] = make_float2(u.z, u.w);
        }
        // stage twiddles: 32 n x 32 mp (512 float4 each)
#pragma unroll
        for (int q = 0; q < 4; q++) {
            int e = t + q * 128;
            int nl = e >> 4, f4 = e & 15;
            size_t gi = (size_t)(k0 + nl) * MP2 + mp0;
            ((float4*)&Cs[nl][0])[f4] = ((const float4*)&g_Bc[gi])[f4];
            ((float4*)&Sn[nl][0])[f4] = ((const float4*)&g_Bs[gi])[f4];
        }
        __syncthreads();
#pragma unroll 4
        for (int q = 0; q < 16; q++) {
            ulonglong2 ce = *(const ulonglong2*)&Cs[2 * q][tc2];
            ulonglong2 co = *(const ulonglong2*)&Cs[2 * q + 1][tc2];
            ulonglong2 se = *(const ulonglong2*)&Sn[2 * q][tc2];
            ulonglong2 so = *(const ulonglong2*)&Sn[2 * q + 1][tc2];
#pragma unroll
            for (int i = 0; i < 4; i++) {
                float2 sv = Ss[trow * 4 + i][q];
                float2 dv = Ds[trow * 4 + i][q];
                ull sae = pk2(sv.x, sv.x), sao = pk2(sv.y, sv.y);
                ull dae = pk2(dv.x, dv.x), dao = pk2(dv.y, dv.y);
                fma2(aCe[i][0], sae, ce.x); fma2(aCe[i][1], sae, ce.y);
                fma2(aCo[i][0], sao, co.x); fma2(aCo[i][1], sao, co.y);
                fma2(aSe[i][0], dae, se.x); fma2(aSe[i][1], dae, se.y);
                fma2(aSo[i][0], dao, so.x); fma2(aSo[i][1], dao, so.y);
            }
        }
        __syncthreads();
    }

    // epilogue: combine partials -> F[m] and F[360-m]
#pragma unroll
    for (int i = 0; i < 4; i++) {
        int gr = row0 + trow * 4 + i;
        if (gr >= R_TOT) continue;
        int tensor = gr / HALF_R;
        int rem = gr - tensor * HALF_R;
        int bc = rem / NLAT;
        int j  = rem - bc * NLAT;
        int c  = tensor * 16 + bc;
        float2* Fc = &g_F[(size_t)c * NLAT + j];   // + m * NCH*NLAT
#pragma unroll
        for (int p = 0; p < 2; p++) {
            int g  = mp0 + tc2 + p;
            int m0 = 2 * g, m1 = m0 + 1;
            float2 ce = upk2(aCe[i][p]), co = upk2(aCo[i][p]);
            float2 se = upk2(aSe[i][p]), so = upk2(aSo[i][p]);
            if (m0 <= 180)
                Fc[(size_t)m0 * (NCH * NLAT)] = make_float2(ce.x + co.x, se.x + so.x);
            if (m1 <= 180)
                Fc[(size_t)m1 * (NCH * NLAT)] = make_float2(ce.y + co.y, se.y + so.y);
            if (m0 <= 179)
                Fc[(size_t)(360 - m0) * (NCH * NLAT)] =
                    make_float2(ce.x - co.x, -se.x + so.x);
            if (m1 <= 179)
                Fc[(size_t)(360 - m1) * (NCH * NLAT)] =
                    make_float2(ce.y - co.y, -se.y + so.y);
        }
    }
}

// ---------------- K2: Legendre contraction, parity fold, 8l x 4ch tile ------
#define TJ 16
__global__ __launch_bounds__(128) void k2_leg(const float* __restrict__ leg) {
    const int m  = blockIdx.y;                 // 0..359
    const int l0 = m + blockIdx.x * 128;
    if (l0 >= KDEG) return;

    __shared__ float2 Fse[TJ][34];             // even-fold F, [j][ch]
    __shared__ float2 Fso[TJ][34];             // odd-fold F
    __shared__ float2 Ls2[128][17];            // leg broadcast pairs {v,v}

    const int t   = threadIdx.x;
    const int cg  = t & 7;
    const int lg  = t >> 3;
    const int ch0 = cg * 4;
    const int lb  = lg * 8;

    ull acc[8][4];
    const ull z = pk2(0.f, 0.f);
#pragma unroll
    for (int i = 0; i < 8; i++)
#pragma unroll
        for (int k = 0; k < 4; k++) acc[i][k] = z;

    const float2* Fm = &g_F[(size_t)m * NCH * NLAT];

    for (int j0 = 0; j0 < 181; j0 += TJ) {     // 12 tiles
#pragma unroll
        for (int q = 0; q < 4; q++) {          // F fold staging (512 entries)
            int p = t + q * 128;
            int c = p >> 4, jl = p & 15;
            int j = j0 + jl;
            float2 f  = (j <= 180) ? Fm[(size_t)c * NLAT + j]       : make_float2(0.f, 0.f);
            float2 fm = (j <  180) ? Fm[(size_t)c * NLAT + 360 - j] : make_float2(0.f, 0.f);
            Fse[jl][c] = make_float2(f.x + fm.x, f.y + fm.y);
            Fso[jl][c] = make_float2(f.x - fm.x, f.y - fm.y);
        }
#pragma unroll
        for (int q = 0; q < 16; q++) {         // leg staging: 128 l x 16 j
            int p  = t + q * 128;
            int lr = p >> 4, jl = p & 15;
            int j  = j0 + jl;
            int l  = l0 + lr;
            float v = (j <= 180 && l <= 360) ? leg[((size_t)l * NLAT + m) * NLAT + j] : 0.f;
            Ls2[lr][jl] = make_float2(v, v);
        }
        __syncthreads();
#pragma unroll 8
        for (int jl = 0; jl < TJ; jl++) {
            ulonglong2 fe01 = *(const ulonglong2*)&Fse[jl][ch0];
            ulonglong2 fe23 = *(const ulonglong2*)&Fse[jl][ch0 + 2];
            ulonglong2 fo01 = *(const ulonglong2*)&Fso[jl][ch0];
            ulonglong2 fo23 = *(const ulonglong2*)&Fso[jl][ch0 + 2];
#pragma unroll
            for (int i = 0; i < 8; i++) {
                ull lv = *(const ull*)&Ls2[lb + i][jl];
                if (i & 1) {
                    fma2(acc[i][0], lv, fo01.x); fma2(acc[i][1], lv, fo01.y);
                    fma2(acc[i][2], lv, fo23.x); fma2(acc[i][3], lv, fo23.y);
                } else {
                    fma2(acc[i][0], lv, fe01.x); fma2(acc[i][1], lv, fe01.y);
                    fma2(acc[i][2], lv, fe23.x); fma2(acc[i][3], lv, fe23.y);
                }
            }
        }
        __syncthreads();
    }

    // epilogue: pair P (cg<4) with T (cg+4) via shfl, atomically accumulate
    const float wm = (m == 0) ? 1.f : 2.f;
#pragma unroll
    for (int i = 0; i < 8; i++) {
        int l = l0 + lb + i;
#pragma unroll
        for (int k = 0; k < 4; k++) {
            float2 cv = upk2(acc[i][k]);
            float ox = __shfl_xor_sync(0xffffffffu, cv.x, 4);
            float oy = __shfl_xor_sync(0xffffffffu, cv.y, 4);
            if (cg < 4 && l < KDEG) {
                float pp  = cv.x * cv.x + cv.y * cv.y;
                float tp  = ox * ox + oy * oy;
                float crr = cv.x * ox + cv.y * oy;
                float cii = cv.x * oy - cv.y * ox;
                float* s = &g_stats[(l * NBC + ch0 + k) * 4];
                atomicAdd(s + 0, wm * pp);
                atomicAdd(s + 1, wm * tp);
                atomicAdd(s + 2, wm * crr);
                atomicAdd(s + 3, wm * cii);
            }
        }
    }
}

// ---------------- K3: final loss --------------------------------------------
__global__ void k3_final(const float* __restrict__ weights, float* __restrict__ out) {
    __shared__ float red[32];
    const int t = threadIdx.x;                 // 1024 threads
    float part = 0.f;
    for (int i = t; i < KDEG * NBC; i += 1024) {
        float4 s = *(const float4*)&g_stats[i * 4];
        int bc = i & 15;
        float pp = s.x + EPSV;
        float tp = s.y + EPSV;
        float mag = sqrtf(s.z * s.z + s.w * s.w);
        float den = sqrtf(pp * tp + EPSV) + EPSV;
        float coh = fminf(mag / den, 1.f);
        float sp = sqrtf(pp), st = sqrtf(tp);
        float amp = (sp - st) * (sp - st);
        float dec = 2.f * fmaxf(pp, tp) * (1.f - coh);
        part += weights[bc & 7] * (amp + dec);
    }
#pragma unroll
    for (int o = 16; o > 0; o >>= 1) part += __shfl_down_sync(0xffffffffu, part, o);
    if ((t & 31) == 0) red[t >> 5] = part;
    __syncthreads();
    if (t < 32) {
        float v = red[t];
#pragma unroll
        for (int o = 16; o > 0; o >>= 1) v += __shfl_down_sync(0xffffffffu, v, o);
        if (t == 0) {
            float loss = v / (float)(KDEG * NBC);
            if (isnan(loss)) loss = 1e6f;
            out[0] = loss;
        }
    }
}

// ---------------- launcher ---------------------------------------------------
extern "C" void kernel_launch(void* const* d_in, const int* in_sizes, int n_in,
                              void* d_out, int out_size) {
    const float* pred    = (const float*)d_in[0];
    const float* targ    = (const float*)d_in[1];
    const float* weights = (const float*)d_in[2];
    const float* leg     = (const float*)d_in[3];
    const float* w       = (const float*)d_in[4];

    k0_tables<<<144, 256>>>();

    int tot0 = R_PAD * (NPAD / 4);
    k0b_sd<<<(tot0 + 255) / 256, 256>>>(pred, targ, w);

    dim3 g1(3, 362);            // 32 mp-tiles x 32-row tiles
    k1_dft<<<g1, 128>>>();

    dim3 g2(3, KDEG);           // 128-l tiles x m
    k2_leg<<<g2, 128>>>(leg);

    k3_final<<<1, 1024>>>(weights, (float*)d_out);
}

// round 7
// speedup vs baseline: 1.9098x; 1.0560x over previous
#include <cuda_runtime.h>
#include <math.h>

#define NLAT 361
#define NLON 720
#define NBC  16        // 2 batches * 8 channels
#define NCH  32        // 2 tensors * 16 complex channels
#define KDEG 360
#define EPSV 1e-7f
#define R_TOT  11552
#define R_PAD  11584   // 362 * 32
#define HALF_R 5776
#define NPAD   384     // padded folded-n dimension (n = 0..360 real)
#define MP2    96      // padded m-pair count (mp 0..90 real -> m 0..181)
#define PI_F 3.14159265358979323846f

typedef unsigned long long ull;

// ---------------- scratch ----------------------------------------------------
__device__ float  g_S[(size_t)R_PAD * NPAD];              // folded sums
__device__ float  g_D[(size_t)R_PAD * NPAD];              // folded diffs
__device__ float2 g_Bc[NPAD * MP2];                       // {cos(m0),cos(m1)}
__device__ float2 g_Bs[NPAD * MP2];                       // {-sin(m0),-sin(m1)}
__device__ float2 g_F[(size_t)NLAT * NCH * NLAT];         // [m][c32][j]
__device__ float  g_stats[KDEG * NBC * 4];                // [l][bc]{pp,tp,sr,si}

// ---------------- f32x2 helpers ---------------------------------------------
__device__ __forceinline__ ull pk2(float x, float y) {
    ull r; asm("mov.b64 %0, {%1, %2};" : "=l"(r) : "f"(x), "f"(y)); return r;
}
__device__ __forceinline__ float2 upk2(ull v) {
    float2 r; asm("mov.b64 {%0, %1}, %2;" : "=f"(r.x), "=f"(r.y) : "l"(v)); return r;
}
__device__ __forceinline__ void fma2(ull &d, ull a, ull b) {
    asm("fma.rn.f32x2 %0, %1, %2, %0;" : "+l"(d) : "l"(a), "l"(b));
}

// ---------------- K0a: twiddle tables (m 0..181) + zero stats ---------------
__global__ void k0_tables() {
    int tid = blockIdx.x * blockDim.x + threadIdx.x;
    int stride = gridDim.x * blockDim.x;
    const int NT = NPAD * MP2;
    for (int i = tid; i < NT; i += stride) {
        int n = i / MP2, mp = i - (i / MP2) * MP2;
        float c0 = 0.f, s0 = 0.f, c1 = 0.f, s1 = 0.f;
        if (n <= 360) {
            int m0 = 2 * mp, m1 = m0 + 1;
            if (m0 <= 181) {
                float s, c;
                sincospif((float)((n * m0) % NLON) / 360.f, &s, &c);
                c0 = c; s0 = -s;
            }
            if (m1 <= 181) {
                float s, c;
                sincospif((float)((n * m1) % NLON) / 360.f, &s, &c);
                c1 = c; s1 = -s;
            }
        }
        g_Bc[i] = make_float2(c0, c1);
        g_Bs[i] = make_float2(s0, s1);
    }
    for (int i = tid; i < KDEG * NBC * 4; i += stride) g_stats[i] = 0.f;
}

// ---------------- K0b: fold rows into sum/diff with quadrature scale --------
__global__ void k0b_sd(const float* __restrict__ pred,
                       const float* __restrict__ targ,
                       const float* __restrict__ w) {
    const int NQ = NPAD / 4;  // 96 float4 per row
    int id = blockIdx.x * blockDim.x + threadIdx.x;
    if (id >= R_PAD * NQ) return;
    int r = id / NQ;
    int n = (id - r * NQ) * 4;
    float4 sv = make_float4(0.f, 0.f, 0.f, 0.f);
    float4 dv = make_float4(0.f, 0.f, 0.f, 0.f);
    if (r < R_TOT) {
        int tensor = r / HALF_R;
        int rem = r - tensor * HALF_R;
        int j = rem % NLAT;
        float wsc = w[j] * (2.f * PI_F / (float)NLON);
        const float* a = (tensor ? targ : pred) + (size_t)rem * NLON;
        float4 af = *(const float4*)(a + n);
        float fa[4] = {af.x, af.y, af.z, af.w};
        float so[4], dd[4];
#pragma unroll
        for (int e = 0; e < 4; e++) {
            int nn = n + e;
            float av = (nn <= 360) ? fa[e] : 0.f;
            float mv = (nn >= 1 && nn <= 359) ? a[NLON - nn] : 0.f;
            so[e] = (av + mv) * wsc;
            dd[e] = (av - mv) * wsc;
        }
        sv = make_float4(so[0], so[1], so[2], so[3]);
        dv = make_float4(dd[0], dd[1], dd[2], dd[3]);
    }
    *(float4*)&g_S[(size_t)r * NPAD + n] = sv;
    *(float4*)&g_D[(size_t)r * NPAD + n] = dv;
}

// ---------------- K1: folded DFT with m <-> 360-m mirror fold ---------------
__global__ __launch_bounds__(128) void k1_dft() {
    __shared__ float2 Ss[32][16];     // [row][q] = {s[2q], s[2q+1]}
    __shared__ float2 Ds[32][16];
    __shared__ float2 Cs[32][32];     // [n_local][mp]
    __shared__ float2 Sn[32][32];

    const int t    = threadIdx.x;
    const int mp0  = blockIdx.x * 32;
    const int row0 = blockIdx.y * 32;
    const int tcol = t & 15;
    const int trow = t >> 4;
    const int tc2  = tcol * 2;

    ull aCe[4][2], aCo[4][2], aSe[4][2], aSo[4][2];
    const ull z = pk2(0.f, 0.f);
#pragma unroll
    for (int i = 0; i < 4; i++)
#pragma unroll
        for (int p = 0; p < 2; p++) {
            aCe[i][p] = z; aCo[i][p] = z; aSe[i][p] = z; aSo[i][p] = z;
        }

    for (int kt = 0; kt < 12; kt++) {
        const int k0 = kt * 32;
#pragma unroll
        for (int q = 0; q < 2; q++) {
            int f = t + q * 128;
            int row = f >> 3, c4 = f & 7;
            size_t gi = (size_t)(row0 + row) * NPAD + k0 + c4 * 4;
            float4 v = *(const float4*)&g_S[gi];
            Ss[row][c4 * 2]     = make_float2(v.x, v.y);
            Ss[row][c4 * 2 + 1] = make_float2(v.z, v.w);
            float4 u = *(const float4*)&g_D[gi];
            Ds[row][c4 * 2]     = make_float2(u.x, u.y);
            Ds[row][c4 * 2 + 1] = make_float2(u.z, u.w);
        }
#pragma unroll
        for (int q = 0; q < 4; q++) {
            int e = t + q * 128;
            int nl = e >> 4, f4 = e & 15;
            size_t gi = (size_t)(k0 + nl) * MP2 + mp0;
            ((float4*)&Cs[nl][0])[f4] = ((const float4*)&g_Bc[gi])[f4];
            ((float4*)&Sn[nl][0])[f4] = ((const float4*)&g_Bs[gi])[f4];
        }
        __syncthreads();
#pragma unroll 4
        for (int q = 0; q < 16; q++) {
            ulonglong2 ce = *(const ulonglong2*)&Cs[2 * q][tc2];
            ulonglong2 co = *(const ulonglong2*)&Cs[2 * q + 1][tc2];
            ulonglong2 se = *(const ulonglong2*)&Sn[2 * q][tc2];
            ulonglong2 so = *(const ulonglong2*)&Sn[2 * q + 1][tc2];
#pragma unroll
            for (int i = 0; i < 4; i++) {
                float2 sv = Ss[trow * 4 + i][q];
                float2 dv = Ds[trow * 4 + i][q];
                ull sae = pk2(sv.x, sv.x), sao = pk2(sv.y, sv.y);
                ull dae = pk2(dv.x, dv.x), dao = pk2(dv.y, dv.y);
                fma2(aCe[i][0], sae, ce.x); fma2(aCe[i][1], sae, ce.y);
                fma2(aCo[i][0], sao, co.x); fma2(aCo[i][1], sao, co.y);
                fma2(aSe[i][0], dae, se.x); fma2(aSe[i][1], dae, se.y);
                fma2(aSo[i][0], dao, so.x); fma2(aSo[i][1], dao, so.y);
            }
        }
        __syncthreads();
    }

#pragma unroll
    for (int i = 0; i < 4; i++) {
        int gr = row0 + trow * 4 + i;
        if (gr >= R_TOT) continue;
        int tensor = gr / HALF_R;
        int rem = gr - tensor * HALF_R;
        int bc = rem / NLAT;
        int j  = rem - bc * NLAT;
        int c  = tensor * 16 + bc;
        float2* Fc = &g_F[(size_t)c * NLAT + j];
#pragma unroll
        for (int p = 0; p < 2; p++) {
            int g  = mp0 + tc2 + p;
            int m0 = 2 * g, m1 = m0 + 1;
            float2 ce = upk2(aCe[i][p]), co = upk2(aCo[i][p]);
            float2 se = upk2(aSe[i][p]), so = upk2(aSo[i][p]);
            if (m0 <= 180)
                Fc[(size_t)m0 * (NCH * NLAT)] = make_float2(ce.x + co.x, se.x + so.x);
            if (m1 <= 180)
                Fc[(size_t)m1 * (NCH * NLAT)] = make_float2(ce.y + co.y, se.y + so.y);
            if (m0 <= 179)
                Fc[(size_t)(360 - m0) * (NCH * NLAT)] =
                    make_float2(ce.x - co.x, -se.x + so.x);
            if (m1 <= 179)
                Fc[(size_t)(360 - m1) * (NCH * NLAT)] =
                    make_float2(ce.y - co.y, -se.y + so.y);
        }
    }
}

// ---------------- K2: Legendre contraction, parity fold, reg double-buffer --
#define TJ 16
#define NTILE 12
__global__ __launch_bounds__(128, 3) void k2_leg(const float* __restrict__ leg) {
    const int m  = blockIdx.y;                 // 0..359
    const int l0 = m + blockIdx.x * 128;
    if (l0 >= KDEG) return;

    __shared__ float2 Fse[TJ][34];             // even-fold F, [j][ch]
    __shared__ float2 Fso[TJ][34];             // odd-fold F
    __shared__ float  Ls[128][TJ + 1];         // leg values (scalar)

    const int t   = threadIdx.x;
    const int cg  = t & 7;
    const int lg  = t >> 3;
    const int ch0 = cg * 4;
    const int lb  = lg * 8;

    const int jl_s = t & 15;                   // staging j index
    const int hi4  = t >> 4;                   // 0..7

    ull acc[8][4];
    const ull z = pk2(0.f, 0.f);
#pragma unroll
    for (int i = 0; i < 8; i++)
#pragma unroll
        for (int k = 0; k < 4; k++) acc[i][k] = z;

    const float2* Fm = &g_F[(size_t)m * NCH * NLAT];

    float2 pf[4], pg[4];                       // F prefetch (4 channels)
    float  pl[16];                             // leg prefetch (16 l rows)

    // ---- prologue: prefetch tile 0 into registers ----
    {
        const int j = jl_s;                    // j0 = 0
#pragma unroll
        for (int q = 0; q < 4; q++) {
            int c = hi4 + 8 * q;
            pf[q] = Fm[(size_t)c * NLAT + j];
            pg[q] = Fm[(size_t)c * NLAT + 360 - j];
        }
#pragma unroll
        for (int q = 0; q < 16; q++) {
            int l = l0 + hi4 + 8 * q;
            pl[q] = (l <= 360) ? leg[((size_t)l * NLAT + m) * NLAT + j] : 0.f;
        }
    }

    for (int tile = 0; tile < NTILE; tile++) {
        // ---- commit prefetched tile to smem ----
#pragma unroll
        for (int q = 0; q < 4; q++) {
            int c = hi4 + 8 * q;
            Fse[jl_s][c] = make_float2(pf[q].x + pg[q].x, pf[q].y + pg[q].y);
            Fso[jl_s][c] = make_float2(pf[q].x - pg[q].x, pf[q].y - pg[q].y);
        }
#pragma unroll
        for (int q = 0; q < 16; q++) Ls[hi4 + 8 * q][jl_s] = pl[q];
        __syncthreads();

        // ---- prefetch next tile (overlaps with compute below) ----
        if (tile + 1 < NTILE) {
            const int j = (tile + 1) * TJ + jl_s;
#pragma unroll
            for (int q = 0; q < 4; q++) {
                int c = hi4 + 8 * q;
                pf[q] = (j <= 180) ? Fm[(size_t)c * NLAT + j]
                                   : make_float2(0.f, 0.f);
                pg[q] = (j <  180) ? Fm[(size_t)c * NLAT + 360 - j]
                                   : make_float2(0.f, 0.f);
            }
#pragma unroll
            for (int q = 0; q < 16; q++) {
                int l = l0 + hi4 + 8 * q;
                pl[q] = (j <= 180 && l <= 360)
                            ? leg[((size_t)l * NLAT + m) * NLAT + j] : 0.f;
            }
        }

        // ---- compute current tile ----
#pragma unroll 4
        for (int jl = 0; jl < TJ; jl++) {
            ulonglong2 fe01 = *(const ulonglong2*)&Fse[jl][ch0];
            ulonglong2 fe23 = *(const ulonglong2*)&Fse[jl][ch0 + 2];
            ulonglong2 fo01 = *(const ulonglong2*)&Fso[jl][ch0];
            ulonglong2 fo23 = *(const ulonglong2*)&Fso[jl][ch0 + 2];
#pragma unroll
            for (int i = 0; i < 8; i++) {
                float lv = Ls[lb + i][jl];
                ull l2 = pk2(lv, lv);
                if (i & 1) {
                    fma2(acc[i][0], l2, fo01.x); fma2(acc[i][1], l2, fo01.y);
                    fma2(acc[i][2], l2, fo23.x); fma2(acc[i][3], l2, fo23.y);
                } else {
                    fma2(acc[i][0], l2, fe01.x); fma2(acc[i][1], l2, fe01.y);
                    fma2(acc[i][2], l2, fe23.x); fma2(acc[i][3], l2, fe23.y);
                }
            }
        }
        __syncthreads();
    }

    // epilogue: pair P (cg<4) with T (cg+4) via shfl, atomically accumulate
    const float wm = (m == 0) ? 1.f : 2.f;
#pragma unroll
    for (int i = 0; i < 8; i++) {
        int l = l0 + lb + i;
#pragma unroll
        for (int k = 0; k < 4; k++) {
            float2 cv = upk2(acc[i][k]);
            float ox = __shfl_xor_sync(0xffffffffu, cv.x, 4);
            float oy = __shfl_xor_sync(0xffffffffu, cv.y, 4);
            if (cg < 4 && l < KDEG) {
                float pp  = cv.x * cv.x + cv.y * cv.y;
                float tp  = ox * ox + oy * oy;
                float crr = cv.x * ox + cv.y * oy;
                float cii = cv.x * oy - cv.y * ox;
                float* s = &g_stats[(l * NBC + ch0 + k) * 4];
                atomicAdd(s + 0, wm * pp);
                atomicAdd(s + 1, wm * tp);
                atomicAdd(s + 2, wm * crr);
                atomicAdd(s + 3, wm * cii);
            }
        }
    }
}

// ---------------- K3: final loss --------------------------------------------
__global__ void k3_final(const float* __restrict__ weights, float* __restrict__ out) {
    __shared__ float red[32];
    const int t = threadIdx.x;                 // 1024 threads
    float part = 0.f;
    for (int i = t; i < KDEG * NBC; i += 1024) {
        float4 s = *(const float4*)&g_stats[i * 4];
        int bc = i & 15;
        float pp = s.x + EPSV;
        float tp = s.y + EPSV;
        float mag = sqrtf(s.z * s.z + s.w * s.w);
        float den = sqrtf(pp * tp + EPSV) + EPSV;
        float coh = fminf(mag / den, 1.f);
        float sp = sqrtf(pp), st = sqrtf(tp);
        float amp = (sp - st) * (sp - st);
        float dec = 2.f * fmaxf(pp, tp) * (1.f - coh);
        part += weights[bc & 7] * (amp + dec);
    }
#pragma unroll
    for (int o = 16; o > 0; o >>= 1) part += __shfl_down_sync(0xffffffffu, part, o);
    if ((t & 31) == 0) red[t >> 5] = part;
    __syncthreads();
    if (t < 32) {
        float v = red[t];
#pragma unroll
        for (int o = 16; o > 0; o >>= 1) v += __shfl_down_sync(0xffffffffu, v, o);
        if (t == 0) {
            float loss = v / (float)(KDEG * NBC);
            if (isnan(loss)) loss = 1e6f;
            out[0] = loss;
        }
    }
}

// ---------------- launcher ---------------------------------------------------
extern "C" void kernel_launch(void* const* d_in, const int* in_sizes, int n_in,
                              void* d_out, int out_size) {
    const float* pred    = (const float*)d_in[0];
    const float* targ    = (const float*)d_in[1];
    const float* weights = (const float*)d_in[2];
    const float* leg     = (const float*)d_in[3];
    const float* w       = (const float*)d_in[4];

    k0_tables<<<144, 256>>>();

    int tot0 = R_PAD * (NPAD / 4);
    k0b_sd<<<(tot0 + 255) / 256, 256>>>(pred, targ, w);

    dim3 g1(3, 362);            // 32 mp-tiles x 32-row tiles
    k1_dft<<<g1, 128>>>();

    dim3 g2(3, KDEG);           // 128-l tiles x m
    k2_leg<<<g2, 128>>>(leg);

    k3_final<<<1, 1024>>>(weights, (float*)d_out);
}